// round 8
// baseline (speedup 1.0000x reference)
#include <cuda_runtime.h>
#include <math.h>

#define N_NODES 50000
#define N_EDGES 800000
#define NTOT    850000   // E + N self loops
#define NGRAPH  256
#define F_IN    64
#define HEADS   4
#define HC      256      // HEADS*F_IN
#define ODIM    128
#define NBLK_SCAN 196    // ceil(N_NODES/256)

// ---------------- scratch (device globals; no allocation) ----------------
__device__ float g_asrc[N_NODES * HEADS];
__device__ float g_adst[N_NODES * HEADS];
__device__ float g_x2  [N_NODES * HC];    // GAT output
__device__ float g_pool[NGRAPH * HC];     // sum exp(gate)*h
__device__ float g_gden[NGRAPH];          // sum exp(gate)
__device__ float g_mean[NGRAPH * HC];     // raw sum of x2
__device__ float g_var [NGRAPH * HC];     // raw sumsq of x2
__device__ float g_wsrc[HC];              // W_h^T att_src_h
__device__ float g_wdst[HC];
__device__ int   g_deg [N_NODES];
__device__ int   g_rowptr[N_NODES + 1];
__device__ int   g_woff[N_NODES];
__device__ int2  g_csr2[NTOT];            // (edge id, src)
__device__ int   g_blk [256];
__device__ int   g_gs  [NGRAPH];
__device__ int   g_ge  [NGRAPH];

// ---------------- init (+ fused prew in last block) ----------------
__global__ void k_init(const float* __restrict__ lin_w,
                       const float* __restrict__ att_src,
                       const float* __restrict__ att_dst) {
    if (blockIdx.x == 256) {
        int t = threadIdx.x;          // t = h*64 + c
        int h = t >> 6, c = t & 63;
        float as = 0.f, ad = 0.f;
        for (int j = 0; j < F_IN; j++) {
            float w = lin_w[(h * F_IN + j) * F_IN + c];
            as += att_src[h * F_IN + j] * w;
            ad += att_dst[h * F_IN + j] * w;
        }
        g_wsrc[t] = as;
        g_wdst[t] = ad;
        return;
    }
    int i = blockIdx.x * blockDim.x + threadIdx.x;
    if (i < N_NODES) g_deg[i] = 0;
    if (i < NGRAPH * HC) { g_mean[i] = 0.f; g_var[i] = 0.f; g_pool[i] = 0.f; }
    if (i < NGRAPH) { g_gs[i] = N_NODES; g_ge[i] = 0; g_gden[i] = 0.f; }
}

// ---------------- front: scores + hist + bounds in one grid ----------------
#define SC_BLKS 6250
#define HI_BLKS 3321
#define BD_BLKS 196
__global__ __launch_bounds__(256) void k_front(const float* __restrict__ x,
                                               const int* __restrict__ ei,
                                               const int* __restrict__ batch) {
    int b = blockIdx.x;
    if (b < SC_BLKS) {
        int warp = threadIdx.x >> 5, lane = threadIdx.x & 31;
        int n = b * 8 + warp;
        if (n >= N_NODES) return;
        float2 xv = *(const float2*)&x[n * F_IN + lane * 2];
        float p0, p1, p2, p3, q0, q1, q2, q3;
        {
            float2 w;
            w = *(const float2*)&g_wsrc[0 * 64 + lane * 2]; p0 = w.x * xv.x + w.y * xv.y;
            w = *(const float2*)&g_wsrc[1 * 64 + lane * 2]; p1 = w.x * xv.x + w.y * xv.y;
            w = *(const float2*)&g_wsrc[2 * 64 + lane * 2]; p2 = w.x * xv.x + w.y * xv.y;
            w = *(const float2*)&g_wsrc[3 * 64 + lane * 2]; p3 = w.x * xv.x + w.y * xv.y;
            w = *(const float2*)&g_wdst[0 * 64 + lane * 2]; q0 = w.x * xv.x + w.y * xv.y;
            w = *(const float2*)&g_wdst[1 * 64 + lane * 2]; q1 = w.x * xv.x + w.y * xv.y;
            w = *(const float2*)&g_wdst[2 * 64 + lane * 2]; q2 = w.x * xv.x + w.y * xv.y;
            w = *(const float2*)&g_wdst[3 * 64 + lane * 2]; q3 = w.x * xv.x + w.y * xv.y;
        }
#pragma unroll
        for (int o = 16; o; o >>= 1) {
            p0 += __shfl_xor_sync(0xFFFFFFFFu, p0, o);
            p1 += __shfl_xor_sync(0xFFFFFFFFu, p1, o);
            p2 += __shfl_xor_sync(0xFFFFFFFFu, p2, o);
            p3 += __shfl_xor_sync(0xFFFFFFFFu, p3, o);
            q0 += __shfl_xor_sync(0xFFFFFFFFu, q0, o);
            q1 += __shfl_xor_sync(0xFFFFFFFFu, q1, o);
            q2 += __shfl_xor_sync(0xFFFFFFFFu, q2, o);
            q3 += __shfl_xor_sync(0xFFFFFFFFu, q3, o);
        }
        if (lane == 0) {
            float4 a = {p0, p1, p2, p3};
            float4 bb = {q0, q1, q2, q3};
            *(float4*)&g_asrc[n * HEADS] = a;
            *(float4*)&g_adst[n * HEADS] = bb;
        }
    } else if (b < SC_BLKS + HI_BLKS) {
        int e = (b - SC_BLKS) * 256 + threadIdx.x;
        if (e >= NTOT) return;
        int dst = (e < N_EDGES) ? ei[N_EDGES + e] : (e - N_EDGES);
        atomicAdd(&g_deg[dst], 1);
    } else {
        int n = (b - SC_BLKS - HI_BLKS) * 256 + threadIdx.x;
        if (n >= N_NODES) return;
        int g = batch[n];
        atomicMin(&g_gs[g], n);
        atomicMax(&g_ge[g], n + 1);
    }
}

// ---------------- CSR scan (2 kernels) ----------------
__global__ void k_scan1() {
    __shared__ int sm[256];
    int b = blockIdx.x, t = threadIdx.x;
    int idx = b * 256 + t;
    int v = (idx < N_NODES) ? g_deg[idx] : 0;
    sm[t] = v;
    __syncthreads();
#pragma unroll
    for (int o = 1; o < 256; o <<= 1) {
        int u = (t >= o) ? sm[t - o] : 0;
        __syncthreads();
        sm[t] += u;
        __syncthreads();
    }
    if (idx < N_NODES) g_rowptr[idx] = sm[t] - v;
    if (t == 255) g_blk[b] = sm[255];
}

__global__ void k_scan23() {
    __shared__ int sm[256];
    int b = blockIdx.x, t = threadIdx.x;
    sm[t] = (t < b) ? g_blk[t] : 0;   // sum of preceding block aggregates
    __syncthreads();
#pragma unroll
    for (int o = 128; o; o >>= 1) {
        if (t < o) sm[t] += sm[t + o];
        __syncthreads();
    }
    int off = sm[0];
    int idx = b * 256 + t;
    if (idx < N_NODES) {
        int r = g_rowptr[idx] + off;
        g_rowptr[idx] = r;
        g_woff[idx] = r;
    }
    if (b == 0 && t == 0) g_rowptr[N_NODES] = NTOT;
}

__global__ void k_fill(const int* __restrict__ ei) {
    int e = blockIdx.x * blockDim.x + threadIdx.x;
    if (e >= NTOT) return;
    int src, dst;
    if (e < N_EDGES) { src = ei[e]; dst = ei[N_EDGES + e]; }
    else             { src = dst = e - N_EDGES; }
    int pos = atomicAdd(&g_woff[dst], 1);
    int2 es; es.x = e; es.y = src;
    g_csr2[pos] = es;
}

// ---------------- fused GAT + W-GEMV + GraphNorm stats ----------------
// grid = 6250 blocks x 256 threads; 8 warps = 8 nodes per block (exact: 6250*8=50000)
#define GAT_WARPS 8
__global__ __launch_bounds__(256) void k_gat(const float* __restrict__ x,
                                             float* __restrict__ alpha,
                                             const float* __restrict__ lin_w,
                                             const float* __restrict__ gat_bias,
                                             const int* __restrict__ batch) {
    __shared__ __align__(16) float s_s[GAT_WARPS * HC];   // aggregated per-head sums, 8KB
    __shared__ int s_b[GAT_WARPS];
    int warp = threadIdx.x >> 5;
    int lane = threadIdx.x & 31;
    int n = blockIdx.x * GAT_WARPS + warp;                // always < N_NODES
    int c0 = lane * 2;

    {   // -------- phase 1: per-warp softmax + raw-x aggregation --------
        int start = g_rowptr[n], end = g_rowptr[n + 1];
        int d = end - start;
        float4 ad = *(const float4*)&g_adst[n * HEADS];
        float2 a0 = {0.f,0.f}, a1 = {0.f,0.f}, a2 = {0.f,0.f}, a3 = {0.f,0.f};

        if (d <= 32) {
            int e = 0, src = 0;
            float4 rv = {-INFINITY, -INFINITY, -INFINITY, -INFINITY};
            if (lane < d) {
                int2 es = g_csr2[start + lane];
                e = es.x; src = es.y;
                float4 as = *(const float4*)&g_asrc[src * HEADS];
                float v;
                v = as.x + ad.x; rv.x = (v > 0.f) ? v : 0.2f * v;
                v = as.y + ad.y; rv.y = (v > 0.f) ? v : 0.2f * v;
                v = as.z + ad.z; rv.z = (v > 0.f) ? v : 0.2f * v;
                v = as.w + ad.w; rv.w = (v > 0.f) ? v : 0.2f * v;
            }
            float m0 = rv.x, m1 = rv.y, m2 = rv.z, m3 = rv.w;
#pragma unroll
            for (int o = 16; o; o >>= 1) {
                m0 = fmaxf(m0, __shfl_xor_sync(0xFFFFFFFFu, m0, o));
                m1 = fmaxf(m1, __shfl_xor_sync(0xFFFFFFFFu, m1, o));
                m2 = fmaxf(m2, __shfl_xor_sync(0xFFFFFFFFu, m2, o));
                m3 = fmaxf(m3, __shfl_xor_sync(0xFFFFFFFFu, m3, o));
            }
            float4 av = {0.f, 0.f, 0.f, 0.f};
            if (lane < d) {
                av.x = __expf(rv.x - m0);
                av.y = __expf(rv.y - m1);
                av.z = __expf(rv.z - m2);
                av.w = __expf(rv.w - m3);
            }
            float s0 = av.x, s1 = av.y, s2 = av.z, s3 = av.w;
#pragma unroll
            for (int o = 16; o; o >>= 1) {
                s0 += __shfl_xor_sync(0xFFFFFFFFu, s0, o);
                s1 += __shfl_xor_sync(0xFFFFFFFFu, s1, o);
                s2 += __shfl_xor_sync(0xFFFFFFFFu, s2, o);
                s3 += __shfl_xor_sync(0xFFFFFFFFu, s3, o);
            }
            av.x *= 1.f / (s0 + 1e-16f);
            av.y *= 1.f / (s1 + 1e-16f);
            av.z *= 1.f / (s2 + 1e-16f);
            av.w *= 1.f / (s3 + 1e-16f);
            if (lane < d) *(float4*)&alpha[e * 4] = av;
#pragma unroll 8
            for (int li = 0; li < d; li++) {
                int sb  = __shfl_sync(0xFFFFFFFFu, src, li);
                float w0 = __shfl_sync(0xFFFFFFFFu, av.x, li);
                float w1 = __shfl_sync(0xFFFFFFFFu, av.y, li);
                float w2 = __shfl_sync(0xFFFFFFFFu, av.z, li);
                float w3 = __shfl_sync(0xFFFFFFFFu, av.w, li);
                float2 xv = *(const float2*)&x[sb * F_IN + c0];
                a0.x += w0 * xv.x; a0.y += w0 * xv.y;
                a1.x += w1 * xv.x; a1.y += w1 * xv.y;
                a2.x += w2 * xv.x; a2.y += w2 * xv.y;
                a3.x += w3 * xv.x; a3.y += w3 * xv.y;
            }
        } else {
            // slow path (rare)
            float m0 = -INFINITY, m1 = -INFINITY, m2 = -INFINITY, m3 = -INFINITY;
            for (int i = start + lane; i < end; i += 32) {
                int2 es = g_csr2[i];
                float4 as = *(const float4*)&g_asrc[es.y * HEADS];
                float v, r;
                v = as.x + ad.x; r = (v > 0.f) ? v : 0.2f * v; m0 = fmaxf(m0, r);
                v = as.y + ad.y; r = (v > 0.f) ? v : 0.2f * v; m1 = fmaxf(m1, r);
                v = as.z + ad.z; r = (v > 0.f) ? v : 0.2f * v; m2 = fmaxf(m2, r);
                v = as.w + ad.w; r = (v > 0.f) ? v : 0.2f * v; m3 = fmaxf(m3, r);
            }
#pragma unroll
            for (int o = 16; o; o >>= 1) {
                m0 = fmaxf(m0, __shfl_xor_sync(0xFFFFFFFFu, m0, o));
                m1 = fmaxf(m1, __shfl_xor_sync(0xFFFFFFFFu, m1, o));
                m2 = fmaxf(m2, __shfl_xor_sync(0xFFFFFFFFu, m2, o));
                m3 = fmaxf(m3, __shfl_xor_sync(0xFFFFFFFFu, m3, o));
            }
            float s0 = 0.f, s1 = 0.f, s2 = 0.f, s3 = 0.f;
            for (int i = start + lane; i < end; i += 32) {
                int2 es = g_csr2[i];
                float4 as = *(const float4*)&g_asrc[es.y * HEADS];
                float v, r; float4 ev;
                v = as.x + ad.x; r = (v > 0.f) ? v : 0.2f * v; ev.x = __expf(r - m0); s0 += ev.x;
                v = as.y + ad.y; r = (v > 0.f) ? v : 0.2f * v; ev.y = __expf(r - m1); s1 += ev.y;
                v = as.z + ad.z; r = (v > 0.f) ? v : 0.2f * v; ev.z = __expf(r - m2); s2 += ev.z;
                v = as.w + ad.w; r = (v > 0.f) ? v : 0.2f * v; ev.w = __expf(r - m3); s3 += ev.w;
                *(float4*)&alpha[es.x * 4] = ev;
            }
#pragma unroll
            for (int o = 16; o; o >>= 1) {
                s0 += __shfl_xor_sync(0xFFFFFFFFu, s0, o);
                s1 += __shfl_xor_sync(0xFFFFFFFFu, s1, o);
                s2 += __shfl_xor_sync(0xFFFFFFFFu, s2, o);
                s3 += __shfl_xor_sync(0xFFFFFFFFu, s3, o);
            }
            float i0 = 1.f / (s0 + 1e-16f), i1 = 1.f / (s1 + 1e-16f);
            float i2 = 1.f / (s2 + 1e-16f), i3 = 1.f / (s3 + 1e-16f);
            for (int base = start; base < end; base += 32) {
                int li = base + lane;
                int cl = min(32, end - base);
                int src = 0; float4 av = {0.f, 0.f, 0.f, 0.f};
                if (li < end) {
                    int2 es = g_csr2[li];
                    src = es.y;
                    av = *(float4*)&alpha[es.x * 4];
                    av.x *= i0; av.y *= i1; av.z *= i2; av.w *= i3;
                    *(float4*)&alpha[es.x * 4] = av;
                }
                for (int k = 0; k < cl; k++) {
                    int sb  = __shfl_sync(0xFFFFFFFFu, src, k);
                    float w0 = __shfl_sync(0xFFFFFFFFu, av.x, k);
                    float w1 = __shfl_sync(0xFFFFFFFFu, av.y, k);
                    float w2 = __shfl_sync(0xFFFFFFFFu, av.z, k);
                    float w3 = __shfl_sync(0xFFFFFFFFu, av.w, k);
                    float2 xv = *(const float2*)&x[sb * F_IN + c0];
                    a0.x += w0 * xv.x; a0.y += w0 * xv.y;
                    a1.x += w1 * xv.x; a1.y += w1 * xv.y;
                    a2.x += w2 * xv.x; a2.y += w2 * xv.y;
                    a3.x += w3 * xv.x; a3.y += w3 * xv.y;
                }
            }
        }
        *(float2*)&s_s[warp * HC + 0 * 64 + c0] = a0;
        *(float2*)&s_s[warp * HC + 1 * 64 + c0] = a1;
        *(float2*)&s_s[warp * HC + 2 * 64 + c0] = a2;
        *(float2*)&s_s[warp * HC + 3 * 64 + c0] = a3;
        if (lane == 0) s_b[warp] = batch[n];
    }
    __syncthreads();

    // -------- phase 2: x2 = W . s + bias  (+ GraphNorm stats) --------
    int j = threadIdx.x;
    float wreg[F_IN];
#pragma unroll
    for (int c = 0; c < F_IN; c++) wreg[c] = lin_w[j * F_IN + c];
    float bj = gat_bias[j];
    int hoff = (j >> 6) * 64;
    int nbase = blockIdx.x * GAT_WARPS;

    float sum = 0.f, sq = 0.f;
    int curg = s_b[0];
#pragma unroll
    for (int nn = 0; nn < GAT_WARPS; nn++) {
        int g = s_b[nn];
        if (g != curg) {
            atomicAdd(&g_mean[curg * HC + j], sum);
            atomicAdd(&g_var[curg * HC + j], sq);
            sum = 0.f; sq = 0.f; curg = g;
        }
        const float4* sp = (const float4*)&s_s[nn * HC + hoff];
        float acc = 0.f;
#pragma unroll
        for (int c4 = 0; c4 < F_IN / 4; c4++) {
            float4 v = sp[c4];
            acc += v.x * wreg[4 * c4] + v.y * wreg[4 * c4 + 1]
                 + v.z * wreg[4 * c4 + 2] + v.w * wreg[4 * c4 + 3];
        }
        acc += bj;
        g_x2[(nbase + nn) * HC + j] = acc;
        sum += acc; sq += acc * acc;
    }
    atomicAdd(&g_mean[curg * HC + j], sum);
    atomicAdd(&g_var[curg * HC + j], sq);
}

// ---------------- fused norm-apply + ReLU + gate MLP + pool accumulate ----------------
#define AG_NPB 16
__global__ __launch_bounds__(256) void k_gatepool(const int* __restrict__ batch,
                                                  const float* __restrict__ mscale,
                                                  const float* __restrict__ gw,
                                                  const float* __restrict__ gb,
                                                  const float* __restrict__ att1_w,
                                                  const float* __restrict__ att1_b,
                                                  const float* __restrict__ att2_w,
                                                  const float* __restrict__ att2_b) {
    __shared__ float wsT[HC * 16];                      // [c][k]
    __shared__ __align__(16) float hs[AG_NPB * HC];
    __shared__ float eg[AG_NPB];
    __shared__ int sb[AG_NPB];
    int j = threadIdx.x;
    for (int t = j; t < 16 * HC; t += 256) {
        int k = t >> 8, c = t & 255;
        wsT[c * 16 + k] = att1_w[t];
    }
    int n0 = blockIdx.x * AG_NPB;
    if (j < AG_NPB) sb[j] = batch[n0 + j];
    float msj = mscale[j], wj = gw[j], bj = gb[j];
    __syncthreads();

    int lastg = -1;
    float cA = 0.f, cB = 0.f;
    for (int nn = 0; nn < AG_NPB; nn++) {
        int g = sb[nn];
        if (g != lastg) {
            float cnt = fmaxf((float)(g_ge[g] - g_gs[g]), 1.f);
            float inv = 1.f / cnt;
            float mean = g_mean[g * HC + j] * inv;
            float ex2 = g_var[g * HC + j] * inv;
            float mm = mean * msj;
            float var = ex2 - 2.f * mm * mean + mm * mm;
            cA = wj * rsqrtf(var + 1e-5f);
            cB = bj - cA * mm;
            lastg = g;
        }
        float h = fmaxf(cA * g_x2[(n0 + nn) * HC + j] + cB, 0.f);
        hs[nn * HC + j] = h;
    }
    __syncthreads();

    {
        int nn = j >> 4, k = j & 15;
        float acc = att1_b[k];
        const float4* hp = (const float4*)&hs[nn * HC];
#pragma unroll 8
        for (int c4 = 0; c4 < HC / 4; c4++) {
            float4 v = hp[c4];
            int c = c4 * 4;
            acc += v.x * wsT[c * 16 + k] + v.y * wsT[(c + 1) * 16 + k]
                 + v.z * wsT[(c + 2) * 16 + k] + v.w * wsT[(c + 3) * 16 + k];
        }
        float r = fmaxf(acc, 0.f) * att2_w[k];
#pragma unroll
        for (int o = 8; o; o >>= 1) r += __shfl_xor_sync(0xFFFFFFFFu, r, o);
        if (k == 0) {
            float gate = 1.f / (1.f + __expf(-(r + att2_b[0])));
            eg[nn] = __expf(gate);
        }
    }
    __syncthreads();

    float pacc = 0.f;
    int curg = sb[0];
    for (int nn = 0; nn < AG_NPB; nn++) {
        int g = sb[nn];
        if (g != curg) {
            atomicAdd(&g_pool[curg * HC + j], pacc);
            pacc = 0.f; curg = g;
        }
        pacc += eg[nn] * hs[nn * HC + j];
    }
    atomicAdd(&g_pool[curg * HC + j], pacc);
    if (j < AG_NPB) atomicAdd(&g_gden[sb[j]], eg[j]);
}

// ---------------- head ----------------
__global__ void k_head(const float* __restrict__ fc1_w, const float* __restrict__ fc1_b,
                       const float* __restrict__ out_w, const float* __restrict__ out_b,
                       float* __restrict__ out) {
    int g = blockIdx.x, o = threadIdx.x;  // 128 threads
    float invZ = 1.f / (g_gden[g] + 1e-16f);
    float acc = fc1_b[o];
    const float* p = &g_pool[g * HC];
    const float* w = &fc1_w[o * HC];
#pragma unroll 8
    for (int c = 0; c < HC; c++) acc += p[c] * invZ * w[c];
    acc = fmaxf(acc, 0.f) * out_w[o];
    __shared__ float red[ODIM];
    red[o] = acc;
    __syncthreads();
#pragma unroll
    for (int s = 64; s; s >>= 1) {
        if (o < s) red[o] += red[o + s];
        __syncthreads();
    }
    if (o == 0) out[g] = 1.f / (1.f + __expf(-(red[0] + out_b[0])));
}

// ---------------- launch ----------------
extern "C" void kernel_launch(void* const* d_in, const int* in_sizes, int n_in,
                              void* d_out, int out_size) {
    const float* x        = (const float*)d_in[0];
    const int*   ei       = (const int*)  d_in[1];
    const int*   batch    = (const int*)  d_in[2];
    const float* lin_w    = (const float*)d_in[3];
    const float* att_src  = (const float*)d_in[4];
    const float* att_dst  = (const float*)d_in[5];
    const float* gat_bias = (const float*)d_in[6];
    const float* gn_w     = (const float*)d_in[7];
    const float* gn_b     = (const float*)d_in[8];
    const float* gn_ms    = (const float*)d_in[9];
    const float* fc1_w    = (const float*)d_in[10];
    const float* fc1_b    = (const float*)d_in[11];
    const float* out_w    = (const float*)d_in[12];
    const float* out_b    = (const float*)d_in[13];
    const float* att1_w   = (const float*)d_in[14];
    const float* att1_b   = (const float*)d_in[15];
    const float* att2_w   = (const float*)d_in[16];
    const float* att2_b   = (const float*)d_in[17];

    float* out   = (float*)d_out;
    float* alpha = out + NGRAPH;   // [NTOT, HEADS]

    k_init<<<257, 256>>>(lin_w, att_src, att_dst);
    k_front<<<SC_BLKS + HI_BLKS + BD_BLKS, 256>>>(x, ei, batch);
    k_scan1<<<NBLK_SCAN, 256>>>();
    k_scan23<<<NBLK_SCAN, 256>>>();
    k_fill<<<(NTOT + 255) / 256, 256>>>(ei);
    k_gat<<<N_NODES / GAT_WARPS, 256>>>(x, alpha, lin_w, gat_bias, batch);
    k_gatepool<<<N_NODES / AG_NPB, 256>>>(batch, gn_ms, gn_w, gn_b,
                                          att1_w, att1_b, att2_w, att2_b);
    k_head<<<NGRAPH, ODIM>>>(fc1_w, fc1_b, out_w, out_b, out);
}

// round 9
// speedup vs baseline: 1.9906x; 1.9906x over previous
#include <cuda_runtime.h>
#include <math.h>

#define N_NODES 50000
#define N_EDGES 800000
#define NTOT    850000   // E + N self loops
#define NGRAPH  256
#define F_IN    64
#define HEADS   4
#define HC      256      // HEADS*F_IN
#define ODIM    128
#define NBLK_SCAN 196    // ceil(N_NODES/256)

// ---------------- scratch (device globals; no allocation) ----------------
__device__ float g_s   [N_NODES * HC];    // per-head weighted x sums
__device__ float g_asrc[N_NODES * HEADS];
__device__ float g_adst[N_NODES * HEADS];
__device__ float g_x2  [N_NODES * HC];    // GAT output
__device__ float g_pool[NGRAPH * HC];     // sum exp(gate)*h
__device__ float g_gden[NGRAPH];          // sum exp(gate)
__device__ float g_mean[NGRAPH * HC];     // raw sum of x2
__device__ float g_var [NGRAPH * HC];     // raw sumsq of x2
__device__ float g_wsrc[HC];              // W_h^T att_src_h
__device__ float g_wdst[HC];
__device__ int   g_deg [N_NODES];
__device__ int   g_rowptr[N_NODES + 1];
__device__ int   g_woff[N_NODES];
__device__ int2  g_csr2[NTOT];            // (edge id, src)
__device__ int   g_blk [256];
__device__ int   g_gs  [NGRAPH];
__device__ int   g_ge  [NGRAPH];

// ---------------- init (+ fused prew in last block) ----------------
__global__ void k_init(const float* __restrict__ lin_w,
                       const float* __restrict__ att_src,
                       const float* __restrict__ att_dst) {
    if (blockIdx.x == 256) {
        int t = threadIdx.x;          // t = h*64 + c
        int h = t >> 6, c = t & 63;
        float as = 0.f, ad = 0.f;
        for (int j = 0; j < F_IN; j++) {
            float w = lin_w[(h * F_IN + j) * F_IN + c];
            as += att_src[h * F_IN + j] * w;
            ad += att_dst[h * F_IN + j] * w;
        }
        g_wsrc[t] = as;
        g_wdst[t] = ad;
        return;
    }
    int i = blockIdx.x * blockDim.x + threadIdx.x;
    if (i < N_NODES) g_deg[i] = 0;
    if (i < NGRAPH * HC) { g_mean[i] = 0.f; g_var[i] = 0.f; g_pool[i] = 0.f; }
    if (i < NGRAPH) { g_gs[i] = N_NODES; g_ge[i] = 0; g_gden[i] = 0.f; }
}

// ---------------- front: scores + hist + bounds in one grid ----------------
#define SC_BLKS 6250
#define HI_BLKS 3321
#define BD_BLKS 196
__global__ __launch_bounds__(256) void k_front(const float* __restrict__ x,
                                               const int* __restrict__ ei,
                                               const int* __restrict__ batch) {
    int b = blockIdx.x;
    if (b < SC_BLKS) {
        int warp = threadIdx.x >> 5, lane = threadIdx.x & 31;
        int n = b * 8 + warp;
        if (n >= N_NODES) return;
        float2 xv = *(const float2*)&x[n * F_IN + lane * 2];
        float p0, p1, p2, p3, q0, q1, q2, q3;
        {
            float2 w;
            w = *(const float2*)&g_wsrc[0 * 64 + lane * 2]; p0 = w.x * xv.x + w.y * xv.y;
            w = *(const float2*)&g_wsrc[1 * 64 + lane * 2]; p1 = w.x * xv.x + w.y * xv.y;
            w = *(const float2*)&g_wsrc[2 * 64 + lane * 2]; p2 = w.x * xv.x + w.y * xv.y;
            w = *(const float2*)&g_wsrc[3 * 64 + lane * 2]; p3 = w.x * xv.x + w.y * xv.y;
            w = *(const float2*)&g_wdst[0 * 64 + lane * 2]; q0 = w.x * xv.x + w.y * xv.y;
            w = *(const float2*)&g_wdst[1 * 64 + lane * 2]; q1 = w.x * xv.x + w.y * xv.y;
            w = *(const float2*)&g_wdst[2 * 64 + lane * 2]; q2 = w.x * xv.x + w.y * xv.y;
            w = *(const float2*)&g_wdst[3 * 64 + lane * 2]; q3 = w.x * xv.x + w.y * xv.y;
        }
#pragma unroll
        for (int o = 16; o; o >>= 1) {
            p0 += __shfl_xor_sync(0xFFFFFFFFu, p0, o);
            p1 += __shfl_xor_sync(0xFFFFFFFFu, p1, o);
            p2 += __shfl_xor_sync(0xFFFFFFFFu, p2, o);
            p3 += __shfl_xor_sync(0xFFFFFFFFu, p3, o);
            q0 += __shfl_xor_sync(0xFFFFFFFFu, q0, o);
            q1 += __shfl_xor_sync(0xFFFFFFFFu, q1, o);
            q2 += __shfl_xor_sync(0xFFFFFFFFu, q2, o);
            q3 += __shfl_xor_sync(0xFFFFFFFFu, q3, o);
        }
        if (lane == 0) {
            float4 a = {p0, p1, p2, p3};
            float4 bb = {q0, q1, q2, q3};
            *(float4*)&g_asrc[n * HEADS] = a;
            *(float4*)&g_adst[n * HEADS] = bb;
        }
    } else if (b < SC_BLKS + HI_BLKS) {
        int e = (b - SC_BLKS) * 256 + threadIdx.x;
        if (e >= NTOT) return;
        int dst = (e < N_EDGES) ? ei[N_EDGES + e] : (e - N_EDGES);
        atomicAdd(&g_deg[dst], 1);
    } else {
        int n = (b - SC_BLKS - HI_BLKS) * 256 + threadIdx.x;
        if (n >= N_NODES) return;
        int g = batch[n];
        atomicMin(&g_gs[g], n);
        atomicMax(&g_ge[g], n + 1);
    }
}

// ---------------- CSR scan (2 kernels) ----------------
__global__ void k_scan1() {
    __shared__ int sm[256];
    int b = blockIdx.x, t = threadIdx.x;
    int idx = b * 256 + t;
    int v = (idx < N_NODES) ? g_deg[idx] : 0;
    sm[t] = v;
    __syncthreads();
#pragma unroll
    for (int o = 1; o < 256; o <<= 1) {
        int u = (t >= o) ? sm[t - o] : 0;
        __syncthreads();
        sm[t] += u;
        __syncthreads();
    }
    if (idx < N_NODES) g_rowptr[idx] = sm[t] - v;
    if (t == 255) g_blk[b] = sm[255];
}

__global__ void k_scan23() {
    __shared__ int sm[256];
    int b = blockIdx.x, t = threadIdx.x;
    sm[t] = (t < b) ? g_blk[t] : 0;   // sum of preceding block aggregates
    __syncthreads();
#pragma unroll
    for (int o = 128; o; o >>= 1) {
        if (t < o) sm[t] += sm[t + o];
        __syncthreads();
    }
    int off = sm[0];
    int idx = b * 256 + t;
    if (idx < N_NODES) {
        int r = g_rowptr[idx] + off;
        g_rowptr[idx] = r;
        g_woff[idx] = r;
    }
    if (b == 0 && t == 0) g_rowptr[N_NODES] = NTOT;
}

__global__ void k_fill(const int* __restrict__ ei) {
    int e = blockIdx.x * blockDim.x + threadIdx.x;
    if (e >= NTOT) return;
    int src, dst;
    if (e < N_EDGES) { src = ei[e]; dst = ei[N_EDGES + e]; }
    else             { src = dst = e - N_EDGES; }
    int pos = atomicAdd(&g_woff[dst], 1);
    int2 es; es.x = e; es.y = src;
    g_csr2[pos] = es;
}

// ---------------- fused GAT: warp per dst node, register-resident ----------------
#define GAT_WARPS 8
__global__ __launch_bounds__(256) void k_gat(const float* __restrict__ x,
                                             float* __restrict__ alpha) {
    int warp = threadIdx.x >> 5;
    int lane = threadIdx.x & 31;
    int n = blockIdx.x * GAT_WARPS + warp;
    if (n >= N_NODES) return;
    int start = g_rowptr[n], end = g_rowptr[n + 1];
    int d = end - start;
    float4 ad = *(const float4*)&g_adst[n * HEADS];
    int c0 = lane * 2;

    float2 a0 = {0.f,0.f}, a1 = {0.f,0.f}, a2 = {0.f,0.f}, a3 = {0.f,0.f};

    if (d <= 32) {
        int e = 0, src = 0;
        float4 rv = {-INFINITY, -INFINITY, -INFINITY, -INFINITY};
        if (lane < d) {
            int2 es = g_csr2[start + lane];
            e = es.x; src = es.y;
            float4 as = *(const float4*)&g_asrc[src * HEADS];
            float v;
            v = as.x + ad.x; rv.x = (v > 0.f) ? v : 0.2f * v;
            v = as.y + ad.y; rv.y = (v > 0.f) ? v : 0.2f * v;
            v = as.z + ad.z; rv.z = (v > 0.f) ? v : 0.2f * v;
            v = as.w + ad.w; rv.w = (v > 0.f) ? v : 0.2f * v;
        }
        float m0 = rv.x, m1 = rv.y, m2 = rv.z, m3 = rv.w;
#pragma unroll
        for (int o = 16; o; o >>= 1) {
            m0 = fmaxf(m0, __shfl_xor_sync(0xFFFFFFFFu, m0, o));
            m1 = fmaxf(m1, __shfl_xor_sync(0xFFFFFFFFu, m1, o));
            m2 = fmaxf(m2, __shfl_xor_sync(0xFFFFFFFFu, m2, o));
            m3 = fmaxf(m3, __shfl_xor_sync(0xFFFFFFFFu, m3, o));
        }
        float4 av = {0.f, 0.f, 0.f, 0.f};
        if (lane < d) {
            av.x = __expf(rv.x - m0);
            av.y = __expf(rv.y - m1);
            av.z = __expf(rv.z - m2);
            av.w = __expf(rv.w - m3);
        }
        float s0 = av.x, s1 = av.y, s2 = av.z, s3 = av.w;
#pragma unroll
        for (int o = 16; o; o >>= 1) {
            s0 += __shfl_xor_sync(0xFFFFFFFFu, s0, o);
            s1 += __shfl_xor_sync(0xFFFFFFFFu, s1, o);
            s2 += __shfl_xor_sync(0xFFFFFFFFu, s2, o);
            s3 += __shfl_xor_sync(0xFFFFFFFFu, s3, o);
        }
        av.x *= 1.f / (s0 + 1e-16f);
        av.y *= 1.f / (s1 + 1e-16f);
        av.z *= 1.f / (s2 + 1e-16f);
        av.w *= 1.f / (s3 + 1e-16f);
        if (lane < d) *(float4*)&alpha[e * 4] = av;

#pragma unroll 8
        for (int li = 0; li < d; li++) {
            int sb  = __shfl_sync(0xFFFFFFFFu, src, li);
            float w0 = __shfl_sync(0xFFFFFFFFu, av.x, li);
            float w1 = __shfl_sync(0xFFFFFFFFu, av.y, li);
            float w2 = __shfl_sync(0xFFFFFFFFu, av.z, li);
            float w3 = __shfl_sync(0xFFFFFFFFu, av.w, li);
            float2 xv = *(const float2*)&x[sb * F_IN + c0];
            a0.x += w0 * xv.x; a0.y += w0 * xv.y;
            a1.x += w1 * xv.x; a1.y += w1 * xv.y;
            a2.x += w2 * xv.x; a2.y += w2 * xv.y;
            a3.x += w3 * xv.x; a3.y += w3 * xv.y;
        }
    } else {
        // slow path (rare): chunked, register-only, 3 passes
        float m0 = -INFINITY, m1 = -INFINITY, m2 = -INFINITY, m3 = -INFINITY;
        for (int i = start + lane; i < end; i += 32) {
            int2 es = g_csr2[i];
            float4 as = *(const float4*)&g_asrc[es.y * HEADS];
            float v, r;
            v = as.x + ad.x; r = (v > 0.f) ? v : 0.2f * v; m0 = fmaxf(m0, r);
            v = as.y + ad.y; r = (v > 0.f) ? v : 0.2f * v; m1 = fmaxf(m1, r);
            v = as.z + ad.z; r = (v > 0.f) ? v : 0.2f * v; m2 = fmaxf(m2, r);
            v = as.w + ad.w; r = (v > 0.f) ? v : 0.2f * v; m3 = fmaxf(m3, r);
        }
#pragma unroll
        for (int o = 16; o; o >>= 1) {
            m0 = fmaxf(m0, __shfl_xor_sync(0xFFFFFFFFu, m0, o));
            m1 = fmaxf(m1, __shfl_xor_sync(0xFFFFFFFFu, m1, o));
            m2 = fmaxf(m2, __shfl_xor_sync(0xFFFFFFFFu, m2, o));
            m3 = fmaxf(m3, __shfl_xor_sync(0xFFFFFFFFu, m3, o));
        }
        float s0 = 0.f, s1 = 0.f, s2 = 0.f, s3 = 0.f;
        for (int i = start + lane; i < end; i += 32) {
            int2 es = g_csr2[i];
            float4 as = *(const float4*)&g_asrc[es.y * HEADS];
            float v, r; float4 ev;
            v = as.x + ad.x; r = (v > 0.f) ? v : 0.2f * v; ev.x = __expf(r - m0); s0 += ev.x;
            v = as.y + ad.y; r = (v > 0.f) ? v : 0.2f * v; ev.y = __expf(r - m1); s1 += ev.y;
            v = as.z + ad.z; r = (v > 0.f) ? v : 0.2f * v; ev.z = __expf(r - m2); s2 += ev.z;
            v = as.w + ad.w; r = (v > 0.f) ? v : 0.2f * v; ev.w = __expf(r - m3); s3 += ev.w;
            *(float4*)&alpha[es.x * 4] = ev;
        }
#pragma unroll
        for (int o = 16; o; o >>= 1) {
            s0 += __shfl_xor_sync(0xFFFFFFFFu, s0, o);
            s1 += __shfl_xor_sync(0xFFFFFFFFu, s1, o);
            s2 += __shfl_xor_sync(0xFFFFFFFFu, s2, o);
            s3 += __shfl_xor_sync(0xFFFFFFFFu, s3, o);
        }
        float i0 = 1.f / (s0 + 1e-16f), i1 = 1.f / (s1 + 1e-16f);
        float i2 = 1.f / (s2 + 1e-16f), i3 = 1.f / (s3 + 1e-16f);
        for (int base = start; base < end; base += 32) {
            int li = base + lane;
            int cl = min(32, end - base);
            int src = 0; float4 av = {0.f, 0.f, 0.f, 0.f};
            if (li < end) {
                int2 es = g_csr2[li];
                src = es.y;
                av = *(float4*)&alpha[es.x * 4];
                av.x *= i0; av.y *= i1; av.z *= i2; av.w *= i3;
                *(float4*)&alpha[es.x * 4] = av;
            }
            for (int k = 0; k < cl; k++) {
                int sb  = __shfl_sync(0xFFFFFFFFu, src, k);
                float w0 = __shfl_sync(0xFFFFFFFFu, av.x, k);
                float w1 = __shfl_sync(0xFFFFFFFFu, av.y, k);
                float w2 = __shfl_sync(0xFFFFFFFFu, av.z, k);
                float w3 = __shfl_sync(0xFFFFFFFFu, av.w, k);
                float2 xv = *(const float2*)&x[sb * F_IN + c0];
                a0.x += w0 * xv.x; a0.y += w0 * xv.y;
                a1.x += w1 * xv.x; a1.y += w1 * xv.y;
                a2.x += w2 * xv.x; a2.y += w2 * xv.y;
                a3.x += w3 * xv.x; a3.y += w3 * xv.y;
            }
        }
    }
    *(float2*)&g_s[n * HC + 0 * 64 + c0] = a0;
    *(float2*)&g_s[n * HC + 1 * 64 + c0] = a1;
    *(float2*)&g_s[n * HC + 2 * 64 + c0] = a2;
    *(float2*)&g_s[n * HC + 3 * 64 + c0] = a3;
}

// ---------------- post-transform + fused GraphNorm stats ----------------
#define PO_NPB 48
__global__ __launch_bounds__(256) void k_post_gn(const float* __restrict__ lin_w,
                                                 const float* __restrict__ gat_bias,
                                                 const int* __restrict__ batch) {
    __shared__ __align__(16) float ss[PO_NPB * HC];   // 48KB
    __shared__ int sb[PO_NPB];
    int j = threadIdx.x;
    float wreg[F_IN];
#pragma unroll
    for (int c = 0; c < F_IN; c++) wreg[c] = lin_w[j * F_IN + c];
    float bj = gat_bias[j];
    int hoff = (j >> 6) * 64;

    int n0 = blockIdx.x * PO_NPB;
    int nmax = min(PO_NPB, N_NODES - n0);
    for (int t = j; t < nmax * HC; t += 256) ss[t] = g_s[n0 * HC + t];
    if (j < nmax) sb[j] = batch[n0 + j];
    __syncthreads();

    float sum = 0.f, sq = 0.f;
    int curg = sb[0];
    for (int nn = 0; nn < nmax; nn++) {
        int g = sb[nn];
        if (g != curg) {
            atomicAdd(&g_mean[curg * HC + j], sum);
            atomicAdd(&g_var[curg * HC + j], sq);
            sum = 0.f; sq = 0.f; curg = g;
        }
        const float4* sp = (const float4*)&ss[nn * HC + hoff];
        float acc = 0.f;
#pragma unroll
        for (int c4 = 0; c4 < F_IN / 4; c4++) {
            float4 v = sp[c4];
            acc += v.x * wreg[4 * c4] + v.y * wreg[4 * c4 + 1]
                 + v.z * wreg[4 * c4 + 2] + v.w * wreg[4 * c4 + 3];
        }
        acc += bj;
        g_x2[(n0 + nn) * HC + j] = acc;
        sum += acc; sq += acc * acc;
    }
    atomicAdd(&g_mean[curg * HC + j], sum);
    atomicAdd(&g_var[curg * HC + j], sq);
}

// ---------------- fused norm-apply + ReLU + gate MLP + pool accumulate ----------------
#define AG_NPB 16
__global__ __launch_bounds__(256) void k_gatepool(const int* __restrict__ batch,
                                                  const float* __restrict__ mscale,
                                                  const float* __restrict__ gw,
                                                  const float* __restrict__ gb,
                                                  const float* __restrict__ att1_w,
                                                  const float* __restrict__ att1_b,
                                                  const float* __restrict__ att2_w,
                                                  const float* __restrict__ att2_b) {
    __shared__ float wsT[HC * 16];                      // [c][k]
    __shared__ __align__(16) float hs[AG_NPB * HC];
    __shared__ float eg[AG_NPB];
    __shared__ int sb[AG_NPB];
    int j = threadIdx.x;
    for (int t = j; t < 16 * HC; t += 256) {
        int k = t >> 8, c = t & 255;
        wsT[c * 16 + k] = att1_w[t];
    }
    int n0 = blockIdx.x * AG_NPB;
    if (j < AG_NPB) sb[j] = batch[n0 + j];
    float msj = mscale[j], wj = gw[j], bj = gb[j];
    __syncthreads();

    int lastg = -1;
    float cA = 0.f, cB = 0.f;
    for (int nn = 0; nn < AG_NPB; nn++) {
        int g = sb[nn];
        if (g != lastg) {
            float cnt = fmaxf((float)(g_ge[g] - g_gs[g]), 1.f);
            float inv = 1.f / cnt;
            float mean = g_mean[g * HC + j] * inv;
            float ex2 = g_var[g * HC + j] * inv;
            float mm = mean * msj;
            float var = ex2 - 2.f * mm * mean + mm * mm;
            cA = wj * rsqrtf(var + 1e-5f);
            cB = bj - cA * mm;
            lastg = g;
        }
        float h = fmaxf(cA * g_x2[(n0 + nn) * HC + j] + cB, 0.f);
        hs[nn * HC + j] = h;
    }
    __syncthreads();

    {
        int nn = j >> 4, k = j & 15;
        float acc = att1_b[k];
        const float4* hp = (const float4*)&hs[nn * HC];
#pragma unroll 8
        for (int c4 = 0; c4 < HC / 4; c4++) {
            float4 v = hp[c4];
            int c = c4 * 4;
            acc += v.x * wsT[c * 16 + k] + v.y * wsT[(c + 1) * 16 + k]
                 + v.z * wsT[(c + 2) * 16 + k] + v.w * wsT[(c + 3) * 16 + k];
        }
        float r = fmaxf(acc, 0.f) * att2_w[k];
#pragma unroll
        for (int o = 8; o; o >>= 1) r += __shfl_xor_sync(0xFFFFFFFFu, r, o);
        if (k == 0) {
            float gate = 1.f / (1.f + __expf(-(r + att2_b[0])));
            eg[nn] = __expf(gate);
        }
    }
    __syncthreads();

    float pacc = 0.f;
    int curg = sb[0];
    for (int nn = 0; nn < AG_NPB; nn++) {
        int g = sb[nn];
        if (g != curg) {
            atomicAdd(&g_pool[curg * HC + j], pacc);
            pacc = 0.f; curg = g;
        }
        pacc += eg[nn] * hs[nn * HC + j];
    }
    atomicAdd(&g_pool[curg * HC + j], pacc);
    if (j < AG_NPB) atomicAdd(&g_gden[sb[j]], eg[j]);
}

// ---------------- head ----------------
__global__ void k_head(const float* __restrict__ fc1_w, const float* __restrict__ fc1_b,
                       const float* __restrict__ out_w, const float* __restrict__ out_b,
                       float* __restrict__ out) {
    int g = blockIdx.x, o = threadIdx.x;  // 128 threads
    float invZ = 1.f / (g_gden[g] + 1e-16f);
    float acc = fc1_b[o];
    const float* p = &g_pool[g * HC];
    const float* w = &fc1_w[o * HC];
#pragma unroll 8
    for (int c = 0; c < HC; c++) acc += p[c] * invZ * w[c];
    acc = fmaxf(acc, 0.f) * out_w[o];
    __shared__ float red[ODIM];
    red[o] = acc;
    __syncthreads();
#pragma unroll
    for (int s = 64; s; s >>= 1) {
        if (o < s) red[o] += red[o + s];
        __syncthreads();
    }
    if (o == 0) out[g] = 1.f / (1.f + __expf(-(red[0] + out_b[0])));
}

// ---------------- launch ----------------
extern "C" void kernel_launch(void* const* d_in, const int* in_sizes, int n_in,
                              void* d_out, int out_size) {
    const float* x        = (const float*)d_in[0];
    const int*   ei       = (const int*)  d_in[1];
    const int*   batch    = (const int*)  d_in[2];
    const float* lin_w    = (const float*)d_in[3];
    const float* att_src  = (const float*)d_in[4];
    const float* att_dst  = (const float*)d_in[5];
    const float* gat_bias = (const float*)d_in[6];
    const float* gn_w     = (const float*)d_in[7];
    const float* gn_b     = (const float*)d_in[8];
    const float* gn_ms    = (const float*)d_in[9];
    const float* fc1_w    = (const float*)d_in[10];
    const float* fc1_b    = (const float*)d_in[11];
    const float* out_w    = (const float*)d_in[12];
    const float* out_b    = (const float*)d_in[13];
    const float* att1_w   = (const float*)d_in[14];
    const float* att1_b   = (const float*)d_in[15];
    const float* att2_w   = (const float*)d_in[16];
    const float* att2_b   = (const float*)d_in[17];

    float* out   = (float*)d_out;
    float* alpha = out + NGRAPH;   // [NTOT, HEADS]

    k_init<<<257, 256>>>(lin_w, att_src, att_dst);
    k_front<<<SC_BLKS + HI_BLKS + BD_BLKS, 256>>>(x, ei, batch);
    k_scan1<<<NBLK_SCAN, 256>>>();
    k_scan23<<<NBLK_SCAN, 256>>>();
    k_fill<<<(NTOT + 255) / 256, 256>>>(ei);
    k_gat<<<(N_NODES + GAT_WARPS - 1) / GAT_WARPS, 256>>>(x, alpha);
    k_post_gn<<<(N_NODES + PO_NPB - 1) / PO_NPB, 256>>>(lin_w, gat_bias, batch);
    k_gatepool<<<N_NODES / AG_NPB, 256>>>(batch, gn_ms, gn_w, gn_b,
                                          att1_w, att1_b, att2_w, att2_b);
    k_head<<<NGRAPH, ODIM>>>(fc1_w, fc1_b, out_w, out_b, out);
}